// round 2
// baseline (speedup 1.0000x reference)
#include <cuda_runtime.h>
#include <math.h>

#define HWN 9216
#define CCH 512
#define NG  32
#define CPG 16

// Scratch (static device globals -- the sanctioned allocation-free workaround)
__device__ float g_hn[CCH * HWN];            // groupnorm output, [C, HW]
__device__ float g_q [CCH * HWN];            // q, [C, HW]
__device__ float g_k [CCH * HWN];            // k, [C, HW]
__device__ float g_v [HWN * CCH];            // v, [HW, C]
__device__ float g_o [HWN * CCH];            // attn output, [HW, C]
__device__ float g_s [(size_t)HWN * HWN];    // scores, [HW, HW]  (340 MB)
__device__ float g_stats[NG * 2];            // per-group mean, rstd

// ---------------------------------------------------------------------------
// GroupNorm: stats (one block per group)
// ---------------------------------------------------------------------------
__global__ void gn_stats_kernel(const float* __restrict__ x) {
    const int g = blockIdx.x;
    const float4* xp = (const float4*)(x + (size_t)g * CPG * HWN);
    const int n4 = (CPG * HWN) / 4;   // 36864
    float s = 0.f, s2 = 0.f;
    for (int i = threadIdx.x; i < n4; i += 256) {
        float4 v = xp[i];
        s  += v.x + v.y + v.z + v.w;
        s2 += v.x * v.x + v.y * v.y + v.z * v.z + v.w * v.w;
    }
    __shared__ float rs[256], rq[256];
    rs[threadIdx.x] = s; rq[threadIdx.x] = s2;
    __syncthreads();
    for (int o = 128; o > 0; o >>= 1) {
        if (threadIdx.x < o) {
            rs[threadIdx.x] += rs[threadIdx.x + o];
            rq[threadIdx.x] += rq[threadIdx.x + o];
        }
        __syncthreads();
    }
    if (threadIdx.x == 0) {
        const float inv  = 1.0f / (float)(CPG * HWN);
        const float mean = rs[0] * inv;
        const float var  = rq[0] * inv - mean * mean;
        g_stats[2 * g]     = mean;
        g_stats[2 * g + 1] = rsqrtf(var + 1e-6f);
    }
}

// ---------------------------------------------------------------------------
// GroupNorm: apply (float4 over [C, HW])
// ---------------------------------------------------------------------------
__global__ void gn_apply_kernel(const float* __restrict__ x,
                                const float* __restrict__ gamma,
                                const float* __restrict__ beta) {
    const int i4 = blockIdx.x * 256 + threadIdx.x;       // float4 index
    const int c  = (i4 * 4) / HWN;                       // HWN % 4 == 0, no crossing
    const int g  = c / CPG;
    const float mean = g_stats[2 * g], rstd = g_stats[2 * g + 1];
    const float ga = gamma[c] * rstd;
    const float be = beta[c] - mean * ga;
    float4 v = ((const float4*)x)[i4];
    v.x = v.x * ga + be; v.y = v.y * ga + be;
    v.z = v.z * ga + be; v.w = v.w * ga + be;
    ((float4*)g_hn)[i4] = v;
}

// ---------------------------------------------------------------------------
// Generic 128x128x8 SGEMM, 256 threads, 8x8 per-thread tile.
// AKM: A is K-major (A[k*lda + m]); else row-major (A[m*lda + k]).
// BKM: B is K-major (B[k*ldb + n]); else row-major (B[n*ldb + k]).
// EPI: 0 = qkv->transposed out [C,HW] (+bias)
//      1 = qkv->row-major out [HW,C] (+bias)
//      2 = scores (scale by alpha), out row-major [HW,HW]
//      3 = AV, out row-major [HW,C]
//      4 = proj (+bias +residual), out transposed [C,HW]
// ---------------------------------------------------------------------------
template <int EPI, bool AKM, bool BKM>
__global__ void __launch_bounds__(256, 2) gemm_kernel(
    const float* __restrict__ A, const float* __restrict__ B,
    const float* __restrict__ bias, const float* __restrict__ resid,
    float* __restrict__ C, int K, int lda, int ldb, float alpha)
{
    const int BM = 128, BN = 128, BK = 8, TM = 8, TN = 8;
    __shared__ float As[BK][BM];
    __shared__ float Bs[BK][BN];

    const int bm = blockIdx.y * BM;
    const int bn = blockIdx.x * BN;
    const int tid = threadIdx.x;
    const int tn = (tid % 16) * TN;
    const int tm = (tid / 16) * TM;

    float acc[TM][TN];
#pragma unroll
    for (int i = 0; i < TM; i++)
#pragma unroll
        for (int j = 0; j < TN; j++) acc[i][j] = 0.f;

    // K-major load pattern: thread -> (k row, 4-wide m/n chunk)
    const int lk  = tid / 32;
    const int lm4 = (tid % 32) * 4;
    // Row-major load pattern: thread -> (m/n row, 4-wide k chunk)
    const int rr = tid / 2;
    const int rk = (tid % 2) * 4;

    for (int k0 = 0; k0 < K; k0 += BK) {
        if (AKM) {
            float4 v = *(const float4*)(A + (size_t)(k0 + lk) * lda + bm + lm4);
            *(float4*)&As[lk][lm4] = v;
        } else {
            float4 v = *(const float4*)(A + (size_t)(bm + rr) * lda + k0 + rk);
            As[rk + 0][rr] = v.x; As[rk + 1][rr] = v.y;
            As[rk + 2][rr] = v.z; As[rk + 3][rr] = v.w;
        }
        if (BKM) {
            float4 v = *(const float4*)(B + (size_t)(k0 + lk) * ldb + bn + lm4);
            *(float4*)&Bs[lk][lm4] = v;
        } else {
            float4 v = *(const float4*)(B + (size_t)(bn + rr) * ldb + k0 + rk);
            Bs[rk + 0][rr] = v.x; Bs[rk + 1][rr] = v.y;
            Bs[rk + 2][rr] = v.z; Bs[rk + 3][rr] = v.w;
        }
        __syncthreads();

#pragma unroll
        for (int k = 0; k < BK; k++) {
            float4 a0 = *(float4*)&As[k][tm];
            float4 a1 = *(float4*)&As[k][tm + 4];
            float4 b0 = *(float4*)&Bs[k][tn];
            float4 b1 = *(float4*)&Bs[k][tn + 4];
            float ar[8] = {a0.x, a0.y, a0.z, a0.w, a1.x, a1.y, a1.z, a1.w};
            float br[8] = {b0.x, b0.y, b0.z, b0.w, b1.x, b1.y, b1.z, b1.w};
#pragma unroll
            for (int i = 0; i < TM; i++)
#pragma unroll
                for (int j = 0; j < TN; j++)
                    acc[i][j] += ar[i] * br[j];
        }
        __syncthreads();
    }

#pragma unroll
    for (int i = 0; i < TM; i++) {
        const int gm = bm + tm + i;
#pragma unroll
        for (int j = 0; j < TN; j++) {
            const int gn = bn + tn + j;
            const float cv = acc[i][j];
            if (EPI == 0)      C[(size_t)gn * HWN + gm] = cv + bias[gn];
            else if (EPI == 1) C[(size_t)gm * CCH + gn] = cv + bias[gn];
            else if (EPI == 2) C[(size_t)gm * HWN + gn] = cv * alpha;
            else if (EPI == 3) C[(size_t)gm * CCH + gn] = cv;
            else               C[(size_t)gn * HWN + gm] = cv + bias[gn] + resid[(size_t)gn * HWN + gm];
        }
    }
}

// ---------------------------------------------------------------------------
// Row softmax: one block per row, full row (36.9 KB) staged in SMEM.
// ---------------------------------------------------------------------------
__global__ void softmax_kernel() {
    __shared__ float4 row[HWN / 4];   // 36864 B
    __shared__ float  red[256];
    const int r   = blockIdx.x;
    const int tid = threadIdx.x;
    float4* sp = (float4*)(g_s + (size_t)r * HWN);

    float mx = -1e30f;
    for (int i = tid; i < HWN / 4; i += 256) {
        float4 v = sp[i];
        row[i] = v;
        mx = fmaxf(mx, fmaxf(fmaxf(v.x, v.y), fmaxf(v.z, v.w)));
    }
    red[tid] = mx; __syncthreads();
    for (int o = 128; o > 0; o >>= 1) {
        if (tid < o) red[tid] = fmaxf(red[tid], red[tid + o]);
        __syncthreads();
    }
    mx = red[0];
    __syncthreads();

    float s = 0.f;
    for (int i = tid; i < HWN / 4; i += 256) {
        float4 v = row[i];
        v.x = __expf(v.x - mx); v.y = __expf(v.y - mx);
        v.z = __expf(v.z - mx); v.w = __expf(v.w - mx);
        row[i] = v;
        s += v.x + v.y + v.z + v.w;
    }
    red[tid] = s; __syncthreads();
    for (int o = 128; o > 0; o >>= 1) {
        if (tid < o) red[tid] += red[tid + o];
        __syncthreads();
    }
    const float inv = 1.0f / red[0];
    __syncthreads();

    for (int i = tid; i < HWN / 4; i += 256) {
        float4 v = row[i];
        v.x *= inv; v.y *= inv; v.z *= inv; v.w *= inv;
        sp[i] = v;
    }
}

// ---------------------------------------------------------------------------
// Launch
// ---------------------------------------------------------------------------
extern "C" void kernel_launch(void* const* d_in, const int* in_sizes, int n_in,
                              void* d_out, int out_size)
{
    const float* x     = (const float*)d_in[0];
    const float* gamma = (const float*)d_in[1];
    const float* beta  = (const float*)d_in[2];
    const float* qw    = (const float*)d_in[3];
    const float* qb    = (const float*)d_in[4];
    const float* kw    = (const float*)d_in[5];
    const float* kb    = (const float*)d_in[6];
    const float* vw    = (const float*)d_in[7];
    const float* vb    = (const float*)d_in[8];
    const float* pw    = (const float*)d_in[9];
    const float* pb    = (const float*)d_in[10];
    float* out = (float*)d_out;

    float *hn, *q, *k, *v, *o, *s;
    cudaGetSymbolAddress((void**)&hn, g_hn);
    cudaGetSymbolAddress((void**)&q,  g_q);
    cudaGetSymbolAddress((void**)&k,  g_k);
    cudaGetSymbolAddress((void**)&v,  g_v);
    cudaGetSymbolAddress((void**)&o,  g_o);
    cudaGetSymbolAddress((void**)&s,  g_s);

    gn_stats_kernel<<<NG, 256>>>(x);
    gn_apply_kernel<<<(CCH * HWN / 4) / 256, 256>>>(x, gamma, beta);

    const dim3 gq(CCH / 128, HWN / 128);   // (4, 72)
    const dim3 gs(HWN / 128, HWN / 128);   // (72, 72)
    const float scale = 0.04419417382415922f;   // 512^-0.5

    // q,k -> [C,HW]; v -> [HW,C]
    gemm_kernel<0, true,  false><<<gq, 256>>>(hn, qw, qb, nullptr, q, CCH, HWN, CCH, 1.f);
    gemm_kernel<0, true,  false><<<gq, 256>>>(hn, kw, kb, nullptr, k, CCH, HWN, CCH, 1.f);
    gemm_kernel<1, true,  false><<<gq, 256>>>(hn, vw, vb, nullptr, v, CCH, HWN, CCH, 1.f);

    // S = scale * q^T k   [HW, HW]
    gemm_kernel<2, true,  true ><<<gs, 256>>>(q, k, nullptr, nullptr, s, CCH, HWN, HWN, scale);

    softmax_kernel<<<HWN, 256>>>();

    // O = softmax(S) @ v  [HW, C]
    gemm_kernel<3, false, true ><<<gq, 256>>>(s, v, nullptr, nullptr, o, HWN, HWN, CCH, 1.f);

    // out = proj(O) + bias + x   [C, HW]
    gemm_kernel<4, false, false><<<gq, 256>>>(o, pw, pb, x, out, CCH, CCH, CCH, 1.f);
}

// round 5
// speedup vs baseline: 1.7812x; 1.7812x over previous
#include <cuda_runtime.h>
#include <cuda_bf16.h>
#include <math.h>
#include <stdint.h>

#define HWN 9216
#define CCH 512
#define NG  32
#define CPG 16

// ---- scratch (static device globals) ----
__device__ float g_hn[(size_t)HWN * CCH];     // groupnorm out, [HW, C]
__device__ float g_q [(size_t)HWN * CCH];     // q, [HW, C]
__device__ float g_k [(size_t)HWN * CCH];     // k, [HW, C]
__device__ float g_v [(size_t)CCH * HWN];     // v, [C, HW]
__device__ float g_o [(size_t)HWN * CCH];     // attn out, [HW, C]
__device__ float g_s [(size_t)HWN * HWN];     // scores, [HW, HW] (340 MB)
__device__ float g_stats[NG * 2];

// ---------------------------------------------------------------------------
// helpers
// ---------------------------------------------------------------------------
__device__ __forceinline__ uint32_t smem_u32(const void* p) {
    uint32_t a;
    asm("{ .reg .u64 t; cvta.to.shared.u64 t, %1; cvt.u32.u64 %0, t; }" : "=r"(a) : "l"(p));
    return a;
}
#define SWZ(x) ((x) ^ (((x) >> 3) & 0x70))

__device__ __forceinline__ void cp_async16(uint32_t saddr, const void* gaddr) {
    asm volatile("cp.async.cg.shared.global [%0], [%1], 16;" :: "r"(saddr), "l"(gaddr));
}
__device__ __forceinline__ void cp_commit() { asm volatile("cp.async.commit_group;"); }
__device__ __forceinline__ void cp_wait0()  { asm volatile("cp.async.wait_group 0;"); }

__device__ __forceinline__ void ldm_x4(uint32_t* r, uint32_t addr) {
    asm volatile("ldmatrix.sync.aligned.m8n8.x4.shared.b16 {%0,%1,%2,%3}, [%4];"
                 : "=r"(r[0]), "=r"(r[1]), "=r"(r[2]), "=r"(r[3]) : "r"(addr));
}
__device__ __forceinline__ void mma16816(float* d, const uint32_t* a, uint32_t b0, uint32_t b1) {
    asm volatile(
        "mma.sync.aligned.m16n8k16.row.col.f32.bf16.bf16.f32 "
        "{%0,%1,%2,%3}, {%4,%5,%6,%7}, {%8,%9}, {%0,%1,%2,%3};"
        : "+f"(d[0]), "+f"(d[1]), "+f"(d[2]), "+f"(d[3])
        : "r"(a[0]), "r"(a[1]), "r"(a[2]), "r"(a[3]), "r"(b0), "r"(b1));
}

__device__ __forceinline__ void split2(float a, float b, uint32_t& hi, uint32_t& lo) {
    __nv_bfloat16 ha = __float2bfloat16(a);
    __nv_bfloat16 hb = __float2bfloat16(b);
    hi = ((uint32_t)__bfloat16_as_ushort(hb) << 16) | (uint32_t)__bfloat16_as_ushort(ha);
    __nv_bfloat16 la = __float2bfloat16(a - __bfloat162float(ha));
    __nv_bfloat16 lb = __float2bfloat16(b - __bfloat162float(hb));
    lo = ((uint32_t)__bfloat16_as_ushort(lb) << 16) | (uint32_t)__bfloat16_as_ushort(la);
}

// ---------------------------------------------------------------------------
// GroupNorm stats
// ---------------------------------------------------------------------------
__global__ void gn_stats_kernel(const float* __restrict__ x) {
    const int g = blockIdx.x;
    const float4* xp = (const float4*)(x + (size_t)g * CPG * HWN);
    const int n4 = (CPG * HWN) / 4;
    float s = 0.f, s2 = 0.f;
    for (int i = threadIdx.x; i < n4; i += 256) {
        float4 v = xp[i];
        s  += v.x + v.y + v.z + v.w;
        s2 += v.x * v.x + v.y * v.y + v.z * v.z + v.w * v.w;
    }
    __shared__ float rs[256], rq[256];
    rs[threadIdx.x] = s; rq[threadIdx.x] = s2;
    __syncthreads();
    for (int o = 128; o > 0; o >>= 1) {
        if (threadIdx.x < o) {
            rs[threadIdx.x] += rs[threadIdx.x + o];
            rq[threadIdx.x] += rq[threadIdx.x + o];
        }
        __syncthreads();
    }
    if (threadIdx.x == 0) {
        const float inv  = 1.0f / (float)(CPG * HWN);
        const float mean = rs[0] * inv;
        const float var  = rq[0] * inv - mean * mean;
        g_stats[2 * g]     = mean;
        g_stats[2 * g + 1] = rsqrtf(var + 1e-6f);
    }
}

// ---------------------------------------------------------------------------
// GroupNorm apply + transpose: x [C, HW] -> hn [HW, C]
// ---------------------------------------------------------------------------
__global__ void gn_apply_t_kernel(const float* __restrict__ x,
                                  const float* __restrict__ gamma,
                                  const float* __restrict__ beta,
                                  float* __restrict__ out) {
    __shared__ float t[32][33];
    const int i0 = blockIdx.x * 32, c0 = blockIdx.y * 32;
    const int tx = threadIdx.x, ty = threadIdx.y;
#pragma unroll
    for (int k = 0; k < 32; k += 8) {
        const int c = c0 + ty + k;
        const int g = c >> 4;
        const float mean = g_stats[2 * g], rstd = g_stats[2 * g + 1];
        const float ga = gamma[c] * rstd;
        const float be = beta[c] - mean * ga;
        t[ty + k][tx] = x[(size_t)c * HWN + i0 + tx] * ga + be;
    }
    __syncthreads();
#pragma unroll
    for (int k = 0; k < 32; k += 8)
        out[(size_t)(i0 + ty + k) * CCH + c0 + tx] = t[tx][ty + k];
}

// ---------------------------------------------------------------------------
// bf16x3 split GEMM on mma.sync (HMMA):  D[M,N] = A[M,K] @ B[N,K]^T
// fp32 in / fp32 out. Tile 128x128, BK=64 (fp32), 8 warps (2x4), 64x32/warp.
// Both operands K-contiguous -> BOTH use non-trans ldmatrix.
// EPI: 0=+bias[n] 1=+bias[m] 2=*alpha 3=none 4=+bias[m]+resid[m*ldc+n]
// ---------------------------------------------------------------------------
#define RAWA_O 0
#define RAWB_O 32768
#define AH_O   65536
#define AL_O   81920
#define BH_O   98304
#define BL_O   114688
#define GEMM_SMEM 131072

template <int EPI>
__global__ void __launch_bounds__(256) gemm_mma(
    const float* __restrict__ A, const float* __restrict__ B,
    const float* __restrict__ bias, const float* __restrict__ resid,
    float* __restrict__ C, int K, int lda, int ldb, int ldc, float alpha)
{
    extern __shared__ char smem[];
    const uint32_t sb = smem_u32(smem);
    const int tid  = threadIdx.x;
    const int lane = tid & 31, warp = tid >> 5;
    const int wm = (warp >> 2) * 64;      // warp row offset in tile
    const int wn = (warp & 3) * 32;       // warp col offset in tile
    const int bm = blockIdx.y * 128;
    const int bn = blockIdx.x * 128;

    float acc[4][4][4];
#pragma unroll
    for (int i = 0; i < 4; i++)
#pragma unroll
        for (int j = 0; j < 4; j++) {
            acc[i][j][0] = 0.f; acc[i][j][1] = 0.f;
            acc[i][j][2] = 0.f; acc[i][j][3] = 0.f;
        }

    const int nch = K >> 6;

    // prologue: stage chunk 0
#pragma unroll
    for (int r = 0; r < 8; r++) {
        const int idx = tid + (r << 8);
        const int row = idx >> 4, c4 = idx & 15;
        cp_async16(sb + RAWA_O + idx * 16, A + (size_t)(bm + row) * lda + (c4 << 2));
        cp_async16(sb + RAWB_O + idx * 16, B + (size_t)(bn + row) * ldb + (c4 << 2));
    }
    cp_commit();

    // ldmatrix source addresses (fixed per thread, byte offsets within plane)
    const int lr  = lane & 7;
    const int sel = lane >> 3;
    // A: matrices (m0k0 -> a0, m8k0 -> a1, m0k8 -> a2, m8k8 -> a3)
    const int a_row = wm + lr + (sel & 1) * 8;
    const int a_kb  = (sel >> 1) * 16;            // bytes
    // B: matrices (n0k0 -> b0, n0k8 -> b1, n8k0 -> b2, n8k8 -> b3)
    const int b_row0 = wn + lr + ((sel >> 1) & 1) * 8;
    const int b_kb   = (sel & 1) * 16;            // bytes

#pragma unroll 1
    for (int ch = 0; ch < nch; ++ch) {
        cp_wait0();
        __syncthreads();

        // convert raw fp32 -> bf16 hi/lo planes (SW128 swizzled, 128B rows)
#pragma unroll
        for (int r = 0; r < 8; r++) {
            const int idx = tid + (r << 8);
            const int row = idx >> 4, c4 = idx & 15;
            const uint32_t off = SWZ((row << 7) + (c4 << 3));
            float4 va = *(float4*)(smem + RAWA_O + idx * 16);
            uint32_t h01, l01, h23, l23;
            split2(va.x, va.y, h01, l01);
            split2(va.z, va.w, h23, l23);
            *(uint2*)(smem + AH_O + off) = make_uint2(h01, h23);
            *(uint2*)(smem + AL_O + off) = make_uint2(l01, l23);
            float4 vb = *(float4*)(smem + RAWB_O + idx * 16);
            split2(vb.x, vb.y, h01, l01);
            split2(vb.z, vb.w, h23, l23);
            *(uint2*)(smem + BH_O + off) = make_uint2(h01, h23);
            *(uint2*)(smem + BL_O + off) = make_uint2(l01, l23);
        }
        __syncthreads();

        // prefetch next chunk into raw buffers (overlaps with compute)
        if (ch + 1 < nch) {
            const int k0n = (ch + 1) << 6;
#pragma unroll
            for (int r = 0; r < 8; r++) {
                const int idx = tid + (r << 8);
                const int row = idx >> 4, c4 = idx & 15;
                cp_async16(sb + RAWA_O + idx * 16,
                           A + (size_t)(bm + row) * lda + k0n + (c4 << 2));
                cp_async16(sb + RAWB_O + idx * 16,
                           B + (size_t)(bn + row) * ldb + k0n + (c4 << 2));
            }
        }
        cp_commit();

        // compute: 4 k16 steps x 3 products x (4 m-tiles x 4 n-tiles)
#pragma unroll
        for (int kk = 0; kk < 4; ++kk) {
            uint32_t ah[4][4], al[4][4], bh[2][4], bl[2][4];
#pragma unroll
            for (int mi = 0; mi < 4; ++mi) {
                const uint32_t off = SWZ(((a_row + mi * 16) << 7) + kk * 32 + a_kb);
                ldm_x4(ah[mi], sb + AH_O + off);
                ldm_x4(al[mi], sb + AL_O + off);
            }
#pragma unroll
            for (int nj = 0; nj < 2; ++nj) {
                const uint32_t off = SWZ(((b_row0 + nj * 16) << 7) + kk * 32 + b_kb);
                ldm_x4(bh[nj], sb + BH_O + off);
                ldm_x4(bl[nj], sb + BL_O + off);
            }
#pragma unroll
            for (int mi = 0; mi < 4; ++mi)
#pragma unroll
                for (int nj = 0; nj < 4; ++nj) {
                    const uint32_t bh0 = bh[nj >> 1][(nj & 1) * 2];
                    const uint32_t bh1 = bh[nj >> 1][(nj & 1) * 2 + 1];
                    const uint32_t bl0 = bl[nj >> 1][(nj & 1) * 2];
                    const uint32_t bl1 = bl[nj >> 1][(nj & 1) * 2 + 1];
                    mma16816(acc[mi][nj], ah[mi], bh0, bh1);
                    mma16816(acc[mi][nj], ah[mi], bl0, bl1);
                    mma16816(acc[mi][nj], al[mi], bh0, bh1);
                }
        }
        __syncthreads();   // planes reused next iteration
    }

    // epilogue: fused, straight from registers
#pragma unroll
    for (int mi = 0; mi < 4; ++mi) {
#pragma unroll
        for (int nj = 0; nj < 4; ++nj) {
            const int r0 = bm + wm + mi * 16 + (lane >> 2);
            const int c0 = bn + wn + nj * 8 + (lane & 3) * 2;
            float v0 = acc[mi][nj][0], v1 = acc[mi][nj][1];
            float v2 = acc[mi][nj][2], v3 = acc[mi][nj][3];
            if (EPI == 0) {
                const float b0 = bias[c0], b1 = bias[c0 + 1];
                v0 += b0; v1 += b1; v2 += b0; v3 += b1;
            } else if (EPI == 1) {
                v0 += bias[r0];     v1 += bias[r0];
                v2 += bias[r0 + 8]; v3 += bias[r0 + 8];
            } else if (EPI == 2) {
                v0 *= alpha; v1 *= alpha; v2 *= alpha; v3 *= alpha;
            } else if (EPI == 4) {
                const float2 ra = *(const float2*)(resid + (size_t)r0 * ldc + c0);
                const float2 rb = *(const float2*)(resid + (size_t)(r0 + 8) * ldc + c0);
                v0 += bias[r0] + ra.x;     v1 += bias[r0] + ra.y;
                v2 += bias[r0 + 8] + rb.x; v3 += bias[r0 + 8] + rb.y;
            }
            *(float2*)(C + (size_t)r0 * ldc + c0)       = make_float2(v0, v1);
            *(float2*)(C + (size_t)(r0 + 8) * ldc + c0) = make_float2(v2, v3);
        }
    }
}

// ---------------------------------------------------------------------------
// Row softmax on g_s (full 36.9 KB row in SMEM)
// ---------------------------------------------------------------------------
__global__ void softmax_kernel() {
    __shared__ float4 row[HWN / 4];
    __shared__ float  red[256];
    const int r = blockIdx.x, tid = threadIdx.x;
    float4* sp = (float4*)(g_s + (size_t)r * HWN);

    float mx = -1e30f;
    for (int i = tid; i < HWN / 4; i += 256) {
        float4 v = sp[i];
        row[i] = v;
        mx = fmaxf(mx, fmaxf(fmaxf(v.x, v.y), fmaxf(v.z, v.w)));
    }
    red[tid] = mx; __syncthreads();
    for (int o = 128; o > 0; o >>= 1) {
        if (tid < o) red[tid] = fmaxf(red[tid], red[tid + o]);
        __syncthreads();
    }
    mx = red[0];
    __syncthreads();

    float s = 0.f;
    for (int i = tid; i < HWN / 4; i += 256) {
        float4 v = row[i];
        v.x = __expf(v.x - mx); v.y = __expf(v.y - mx);
        v.z = __expf(v.z - mx); v.w = __expf(v.w - mx);
        row[i] = v;
        s += v.x + v.y + v.z + v.w;
    }
    red[tid] = s; __syncthreads();
    for (int o = 128; o > 0; o >>= 1) {
        if (tid < o) red[tid] += red[tid + o];
        __syncthreads();
    }
    const float inv = 1.0f / red[0];
    __syncthreads();

    for (int i = tid; i < HWN / 4; i += 256) {
        float4 v = row[i];
        v.x *= inv; v.y *= inv; v.z *= inv; v.w *= inv;
        sp[i] = v;
    }
}

// ---------------------------------------------------------------------------
// Launch
// ---------------------------------------------------------------------------
extern "C" void kernel_launch(void* const* d_in, const int* in_sizes, int n_in,
                              void* d_out, int out_size)
{
    const float* x     = (const float*)d_in[0];
    const float* gamma = (const float*)d_in[1];
    const float* beta  = (const float*)d_in[2];
    const float* qw    = (const float*)d_in[3];
    const float* qb    = (const float*)d_in[4];
    const float* kw    = (const float*)d_in[5];
    const float* kb    = (const float*)d_in[6];
    const float* vw    = (const float*)d_in[7];
    const float* vb    = (const float*)d_in[8];
    const float* pw    = (const float*)d_in[9];
    const float* pb    = (const float*)d_in[10];
    float* out = (float*)d_out;

    float *hn, *q, *k, *v, *o, *s;
    cudaGetSymbolAddress((void**)&hn, g_hn);
    cudaGetSymbolAddress((void**)&q,  g_q);
    cudaGetSymbolAddress((void**)&k,  g_k);
    cudaGetSymbolAddress((void**)&v,  g_v);
    cudaGetSymbolAddress((void**)&o,  g_o);
    cudaGetSymbolAddress((void**)&s,  g_s);

    cudaFuncSetAttribute(gemm_mma<0>, cudaFuncAttributeMaxDynamicSharedMemorySize, GEMM_SMEM);
    cudaFuncSetAttribute(gemm_mma<1>, cudaFuncAttributeMaxDynamicSharedMemorySize, GEMM_SMEM);
    cudaFuncSetAttribute(gemm_mma<2>, cudaFuncAttributeMaxDynamicSharedMemorySize, GEMM_SMEM);
    cudaFuncSetAttribute(gemm_mma<3>, cudaFuncAttributeMaxDynamicSharedMemorySize, GEMM_SMEM);
    cudaFuncSetAttribute(gemm_mma<4>, cudaFuncAttributeMaxDynamicSharedMemorySize, GEMM_SMEM);

    gn_stats_kernel<<<NG, 256>>>(x);
    gn_apply_t_kernel<<<dim3(HWN / 32, CCH / 32), dim3(32, 8)>>>(x, gamma, beta, hn);

    const float scale = 0.04419417382415922f;  // 512^-0.5

    // Q = hn @ qw^T  [HW, C]
    gemm_mma<0><<<dim3(4, 72), 256, GEMM_SMEM>>>(hn, qw, qb, nullptr, q, CCH, CCH, CCH, CCH, 0.f);
    // K = hn @ kw^T  [HW, C]
    gemm_mma<0><<<dim3(4, 72), 256, GEMM_SMEM>>>(hn, kw, kb, nullptr, k, CCH, CCH, CCH, CCH, 0.f);
    // V = vw @ hn^T  [C, HW]
    gemm_mma<1><<<dim3(72, 4), 256, GEMM_SMEM>>>(vw, hn, vb, nullptr, v, CCH, CCH, CCH, HWN, 0.f);
    // S = scale * (Q @ K^T)  [HW, HW]
    gemm_mma<2><<<dim3(72, 72), 256, GEMM_SMEM>>>(q, k, nullptr, nullptr, s, CCH, CCH, CCH, HWN, scale);

    softmax_kernel<<<HWN, 256>>>();

    // O = attn @ v^T  [HW, C]
    gemm_mma<3><<<dim3(4, 72), 256, GEMM_SMEM>>>(s, v, nullptr, nullptr, o, HWN, HWN, HWN, CCH, 0.f);
    // out = pw @ O^T + pb + x  [C, HW]
    gemm_mma<4><<<dim3(72, 4), 256, GEMM_SMEM>>>(pw, o, pb, x, out, CCH, CCH, CCH, HWN, 0.f);
}

// round 6
// speedup vs baseline: 2.7060x; 1.5192x over previous
#include <cuda_runtime.h>
#include <cuda_bf16.h>
#include <math.h>
#include <stdint.h>

#define HWN 9216
#define CCH 512
#define NG  32
#define CPG 16

typedef __nv_bfloat16 bf16;

// ---- scratch (static device globals) ----
__device__ float g_s [(size_t)HWN * HWN];          // fp32 scores (340 MB)
__device__ bf16  g_sh[(size_t)HWN * HWN];          // softmax hi plane
__device__ bf16  g_sl[(size_t)HWN * HWN];          // softmax lo plane
__device__ bf16  g_hnh[(size_t)HWN * CCH], g_hnl[(size_t)HWN * CCH];
__device__ bf16  g_qh [(size_t)HWN * CCH], g_ql [(size_t)HWN * CCH];
__device__ bf16  g_kh [(size_t)HWN * CCH], g_kl [(size_t)HWN * CCH];
__device__ bf16  g_vh [(size_t)CCH * HWN], g_vl [(size_t)CCH * HWN];
__device__ bf16  g_oh [(size_t)HWN * CCH], g_ol [(size_t)HWN * CCH];
__device__ bf16  g_qwh[CCH * CCH], g_qwl[CCH * CCH];
__device__ bf16  g_kwh[CCH * CCH], g_kwl[CCH * CCH];
__device__ bf16  g_vwh[CCH * CCH], g_vwl[CCH * CCH];
__device__ bf16  g_pwh[CCH * CCH], g_pwl[CCH * CCH];
__device__ float g_stats[NG * 2];

// ---------------------------------------------------------------------------
// helpers
// ---------------------------------------------------------------------------
__device__ __forceinline__ uint32_t smem_u32(const void* p) {
    uint32_t a;
    asm("{ .reg .u64 t; cvta.to.shared.u64 t, %1; cvt.u32.u64 %0, t; }" : "=r"(a) : "l"(p));
    return a;
}
#define SWZ(x) ((x) ^ (((x) >> 3) & 0x70))

__device__ __forceinline__ void cp_async16(uint32_t saddr, const void* gaddr) {
    asm volatile("cp.async.cg.shared.global [%0], [%1], 16;" :: "r"(saddr), "l"(gaddr));
}
__device__ __forceinline__ void cp_commit() { asm volatile("cp.async.commit_group;"); }
#define CP_WAIT1() asm volatile("cp.async.wait_group 1;")

__device__ __forceinline__ void ldm_x4(uint32_t* r, uint32_t addr) {
    asm volatile("ldmatrix.sync.aligned.m8n8.x4.shared.b16 {%0,%1,%2,%3}, [%4];"
                 : "=r"(r[0]), "=r"(r[1]), "=r"(r[2]), "=r"(r[3]) : "r"(addr));
}
__device__ __forceinline__ void mma16816(float* d, const uint32_t* a, uint32_t b0, uint32_t b1) {
    asm volatile(
        "mma.sync.aligned.m16n8k16.row.col.f32.bf16.bf16.f32 "
        "{%0,%1,%2,%3}, {%4,%5,%6,%7}, {%8,%9}, {%0,%1,%2,%3};"
        : "+f"(d[0]), "+f"(d[1]), "+f"(d[2]), "+f"(d[3])
        : "r"(a[0]), "r"(a[1]), "r"(a[2]), "r"(a[3]), "r"(b0), "r"(b1));
}

__device__ __forceinline__ void split2(float a, float b, uint32_t& hi, uint32_t& lo) {
    bf16 ha = __float2bfloat16(a);
    bf16 hb = __float2bfloat16(b);
    hi = ((uint32_t)__bfloat16_as_ushort(hb) << 16) | (uint32_t)__bfloat16_as_ushort(ha);
    bf16 la = __float2bfloat16(a - __bfloat162float(ha));
    bf16 lb = __float2bfloat16(b - __bfloat162float(hb));
    lo = ((uint32_t)__bfloat16_as_ushort(lb) << 16) | (uint32_t)__bfloat16_as_ushort(la);
}

// ---------------------------------------------------------------------------
// GroupNorm stats
// ---------------------------------------------------------------------------
__global__ void gn_stats_kernel(const float* __restrict__ x) {
    const int g = blockIdx.x;
    const float4* xp = (const float4*)(x + (size_t)g * CPG * HWN);
    const int n4 = (CPG * HWN) / 4;
    float s = 0.f, s2 = 0.f;
    for (int i = threadIdx.x; i < n4; i += 256) {
        float4 v = xp[i];
        s  += v.x + v.y + v.z + v.w;
        s2 += v.x * v.x + v.y * v.y + v.z * v.z + v.w * v.w;
    }
    __shared__ float rs[256], rq[256];
    rs[threadIdx.x] = s; rq[threadIdx.x] = s2;
    __syncthreads();
    for (int o = 128; o > 0; o >>= 1) {
        if (threadIdx.x < o) {
            rs[threadIdx.x] += rs[threadIdx.x + o];
            rq[threadIdx.x] += rq[threadIdx.x + o];
        }
        __syncthreads();
    }
    if (threadIdx.x == 0) {
        const float inv  = 1.0f / (float)(CPG * HWN);
        const float mean = rs[0] * inv;
        const float var  = rq[0] * inv - mean * mean;
        g_stats[2 * g]     = mean;
        g_stats[2 * g + 1] = rsqrtf(var + 1e-6f);
    }
}

// ---------------------------------------------------------------------------
// GroupNorm apply + transpose + split: x [C, HW] -> hn hi/lo planes [HW, C]
// ---------------------------------------------------------------------------
__global__ void gn_apply_t_kernel(const float* __restrict__ x,
                                  const float* __restrict__ gamma,
                                  const float* __restrict__ beta,
                                  bf16* __restrict__ ohi, bf16* __restrict__ olo) {
    __shared__ float t[32][33];
    const int i0 = blockIdx.x * 32, c0 = blockIdx.y * 32;
    const int tx = threadIdx.x, ty = threadIdx.y;
#pragma unroll
    for (int k = 0; k < 32; k += 8) {
        const int c = c0 + ty + k;
        const int g = c >> 4;
        const float mean = g_stats[2 * g], rstd = g_stats[2 * g + 1];
        const float ga = gamma[c] * rstd;
        const float be = beta[c] - mean * ga;
        t[ty + k][tx] = x[(size_t)c * HWN + i0 + tx] * ga + be;
    }
    __syncthreads();
#pragma unroll
    for (int k = 0; k < 32; k += 8) {
        const float val = t[tx][ty + k];
        const bf16 h = __float2bfloat16(val);
        const size_t idx = (size_t)(i0 + ty + k) * CCH + c0 + tx;
        ohi[idx] = h;
        olo[idx] = __float2bfloat16(val - __bfloat162float(h));
    }
}

// ---------------------------------------------------------------------------
// elementwise split fp32 -> bf16 hi/lo (for weights)
// ---------------------------------------------------------------------------
__global__ void split_kernel(const float* __restrict__ w,
                             bf16* __restrict__ hi, bf16* __restrict__ lo, int n) {
    const int i = blockIdx.x * 256 + threadIdx.x;
    if (i < n) {
        const float v = w[i];
        const bf16 h = __float2bfloat16(v);
        hi[i] = h;
        lo[i] = __float2bfloat16(v - __bfloat162float(h));
    }
}

// ---------------------------------------------------------------------------
// Plain bf16 GEMM with virtual K' = 3K (split-x3 via plane selection):
//   seg 0: Ahi*Bhi   seg 1: Ahi*Blo   seg 2: Alo*Bhi
// D[M,N] = A[M,K] @ B[N,K]^T ; tile 128x128, BK=64 bf16, 3-stage cp.async.
// EPI: 0 = split-out + bias[n]     1 = split-out + bias[m]
//      2 = fp32-out * alpha        3 = split-out, no bias
//      4 = fp32-out + bias[m] + resid[m*ldc+n]
// SMEM: 3 stages x (A 16KB + B 16KB) = 96 KB -> 2 CTAs/SM
// ---------------------------------------------------------------------------
#define STG_A(s) ((s) * 16384)
#define STG_B(s) (49152 + (s) * 16384)
#define GEMM_SMEM 98304

__device__ __forceinline__ void load_stage(
    uint32_t sbA, uint32_t sbB,
    const bf16* __restrict__ Ap, const bf16* __restrict__ Bp,
    int bm, int bn, int lda, int ldb, int k0, int tid)
{
#pragma unroll
    for (int r = 0; r < 4; r++) {
        const int idx = tid + (r << 8);        // 0..1023
        const int row = idx >> 3, c8 = idx & 7;
        const uint32_t off = SWZ((row << 7) + (c8 << 4));
        cp_async16(sbA + off, Ap + (size_t)(bm + row) * lda + k0 + (c8 << 3));
        cp_async16(sbB + off, Bp + (size_t)(bn + row) * ldb + k0 + (c8 << 3));
    }
}

template <int EPI>
__global__ void __launch_bounds__(256, 2) gemm_bf16(
    const bf16* __restrict__ Ahi, const bf16* __restrict__ Alo,
    const bf16* __restrict__ Bhi, const bf16* __restrict__ Blo,
    const float* __restrict__ bias, const float* __restrict__ resid,
    float* __restrict__ Cf, bf16* __restrict__ Chi, bf16* __restrict__ Clo,
    int K, int lda, int ldb, int ldc, float alpha)
{
    extern __shared__ char smem[];
    const uint32_t sb = smem_u32(smem);
    const int tid  = threadIdx.x;
    const int lane = tid & 31, warp = tid >> 5;
    const int wm = (warp >> 2) * 64;
    const int wn = (warp & 3) * 32;
    const int bm = blockIdx.y * 128;
    const int bn = blockIdx.x * 128;

    float acc[4][4][4];
#pragma unroll
    for (int i = 0; i < 4; i++)
#pragma unroll
        for (int j = 0; j < 4; j++) {
            acc[i][j][0] = 0.f; acc[i][j][1] = 0.f;
            acc[i][j][2] = 0.f; acc[i][j][3] = 0.f;
        }

    const int KC  = K >> 6;
    const int NCH = 3 * KC;

    // prologue: chunks 0,1 are always in segment 0 (KC >= 8)
    load_stage(sb + STG_A(0), sb + STG_B(0), Ahi, Bhi, bm, bn, lda, ldb, 0,  tid);
    cp_commit();
    load_stage(sb + STG_A(1), sb + STG_B(1), Ahi, Bhi, bm, bn, lda, ldb, 64, tid);
    cp_commit();

    // ldmatrix per-thread addresses
    const int lr  = lane & 7;
    const int sel = lane >> 3;
    const int a_row  = wm + lr + (sel & 1) * 8;
    const int a_kb   = (sel >> 1) * 16;
    const int b_row0 = wn + lr + ((sel >> 1) & 1) * 8;
    const int b_kb   = (sel & 1) * 16;

#pragma unroll 1
    for (int c = 0; c < NCH; ++c) {
        CP_WAIT1();
        __syncthreads();

        const int cn = c + 2;
        if (cn < NCH) {
            const int seg = cn / KC;
            const int k0  = (cn - seg * KC) << 6;
            const bf16* Ap = (seg == 2) ? Alo : Ahi;
            const bf16* Bp = (seg == 1) ? Blo : Bhi;
            const int s = cn % 3;
            load_stage(sb + STG_A(s), sb + STG_B(s), Ap, Bp, bm, bn, lda, ldb, k0, tid);
        }
        cp_commit();

        const uint32_t sA = sb + STG_A(c % 3);
        const uint32_t sB = sb + STG_B(c % 3);
#pragma unroll
        for (int kk = 0; kk < 4; ++kk) {
            uint32_t af[4][4], bfr[2][4];
#pragma unroll
            for (int mi = 0; mi < 4; ++mi)
                ldm_x4(af[mi], sA + SWZ(((a_row + mi * 16) << 7) + kk * 32 + a_kb));
#pragma unroll
            for (int nj = 0; nj < 2; ++nj)
                ldm_x4(bfr[nj], sB + SWZ(((b_row0 + nj * 16) << 7) + kk * 32 + b_kb));
#pragma unroll
            for (int mi = 0; mi < 4; ++mi)
#pragma unroll
                for (int nj = 0; nj < 4; ++nj)
                    mma16816(acc[mi][nj], af[mi],
                             bfr[nj >> 1][(nj & 1) * 2], bfr[nj >> 1][(nj & 1) * 2 + 1]);
        }
        __syncthreads();
    }

    // epilogue
#pragma unroll
    for (int mi = 0; mi < 4; ++mi) {
#pragma unroll
        for (int nj = 0; nj < 4; ++nj) {
            const int r0 = bm + wm + mi * 16 + (lane >> 2);
            const int c0 = bn + wn + nj * 8 + (lane & 3) * 2;
            float v0 = acc[mi][nj][0], v1 = acc[mi][nj][1];
            float v2 = acc[mi][nj][2], v3 = acc[mi][nj][3];
            if (EPI == 0) {
                const float b0 = bias[c0], b1 = bias[c0 + 1];
                v0 += b0; v1 += b1; v2 += b0; v3 += b1;
            } else if (EPI == 1) {
                v0 += bias[r0];     v1 += bias[r0];
                v2 += bias[r0 + 8]; v3 += bias[r0 + 8];
            } else if (EPI == 2) {
                v0 *= alpha; v1 *= alpha; v2 *= alpha; v3 *= alpha;
            } else if (EPI == 4) {
                const float2 ra = *(const float2*)(resid + (size_t)r0 * ldc + c0);
                const float2 rb = *(const float2*)(resid + (size_t)(r0 + 8) * ldc + c0);
                v0 += bias[r0] + ra.x;     v1 += bias[r0] + ra.y;
                v2 += bias[r0 + 8] + rb.x; v3 += bias[r0 + 8] + rb.y;
            }
            if (EPI == 2 || EPI == 4) {
                *(float2*)(Cf + (size_t)r0 * ldc + c0)       = make_float2(v0, v1);
                *(float2*)(Cf + (size_t)(r0 + 8) * ldc + c0) = make_float2(v2, v3);
            } else {
                uint32_t h01, l01, h23, l23;
                split2(v0, v1, h01, l01);
                split2(v2, v3, h23, l23);
                *(uint32_t*)(Chi + (size_t)r0 * ldc + c0)       = h01;
                *(uint32_t*)(Clo + (size_t)r0 * ldc + c0)       = l01;
                *(uint32_t*)(Chi + (size_t)(r0 + 8) * ldc + c0) = h23;
                *(uint32_t*)(Clo + (size_t)(r0 + 8) * ldc + c0) = l23;
            }
        }
    }
}

// ---------------------------------------------------------------------------
// Row softmax: read fp32 g_s row, write bf16 hi/lo planes
// ---------------------------------------------------------------------------
__global__ void softmax_kernel() {
    __shared__ float4 row[HWN / 4];
    __shared__ float  red[256];
    const int r = blockIdx.x, tid = threadIdx.x;
    const float4* sp = (const float4*)(g_s + (size_t)r * HWN);

    float mx = -1e30f;
    for (int i = tid; i < HWN / 4; i += 256) {
        float4 v = sp[i];
        row[i] = v;
        mx = fmaxf(mx, fmaxf(fmaxf(v.x, v.y), fmaxf(v.z, v.w)));
    }
    red[tid] = mx; __syncthreads();
    for (int o = 128; o > 0; o >>= 1) {
        if (tid < o) red[tid] = fmaxf(red[tid], red[tid + o]);
        __syncthreads();
    }
    mx = red[0];
    __syncthreads();

    float s = 0.f;
    for (int i = tid; i < HWN / 4; i += 256) {
        float4 v = row[i];
        v.x = __expf(v.x - mx); v.y = __expf(v.y - mx);
        v.z = __expf(v.z - mx); v.w = __expf(v.w - mx);
        row[i] = v;
        s += v.x + v.y + v.z + v.w;
    }
    red[tid] = s; __syncthreads();
    for (int o = 128; o > 0; o >>= 1) {
        if (tid < o) red[tid] += red[tid + o];
        __syncthreads();
    }
    const float inv = 1.0f / red[0];
    __syncthreads();

    uint2* shp = (uint2*)(g_sh + (size_t)r * HWN);
    uint2* slp = (uint2*)(g_sl + (size_t)r * HWN);
    for (int i = tid; i < HWN / 4; i += 256) {
        float4 v = row[i];
        v.x *= inv; v.y *= inv; v.z *= inv; v.w *= inv;
        uint32_t h01, l01, h23, l23;
        split2(v.x, v.y, h01, l01);
        split2(v.z, v.w, h23, l23);
        shp[i] = make_uint2(h01, h23);
        slp[i] = make_uint2(l01, l23);
    }
}

// ---------------------------------------------------------------------------
// Launch
// ---------------------------------------------------------------------------
extern "C" void kernel_launch(void* const* d_in, const int* in_sizes, int n_in,
                              void* d_out, int out_size)
{
    const float* x     = (const float*)d_in[0];
    const float* gamma = (const float*)d_in[1];
    const float* beta  = (const float*)d_in[2];
    const float* qw    = (const float*)d_in[3];
    const float* qb    = (const float*)d_in[4];
    const float* kw    = (const float*)d_in[5];
    const float* kb    = (const float*)d_in[6];
    const float* vw    = (const float*)d_in[7];
    const float* vb    = (const float*)d_in[8];
    const float* pw    = (const float*)d_in[9];
    const float* pb    = (const float*)d_in[10];
    float* out = (float*)d_out;

    float* s;
    bf16 *hnh, *hnl, *qh, *ql, *kh, *kl, *vh, *vl, *oh, *ol, *sh, *sl;
    bf16 *qwh, *qwl, *kwh, *kwl, *vwh, *vwl, *pwh, *pwl;
    cudaGetSymbolAddress((void**)&s,   g_s);
    cudaGetSymbolAddress((void**)&sh,  g_sh);
    cudaGetSymbolAddress((void**)&sl,  g_sl);
    cudaGetSymbolAddress((void**)&hnh, g_hnh); cudaGetSymbolAddress((void**)&hnl, g_hnl);
    cudaGetSymbolAddress((void**)&qh,  g_qh);  cudaGetSymbolAddress((void**)&ql,  g_ql);
    cudaGetSymbolAddress((void**)&kh,  g_kh);  cudaGetSymbolAddress((void**)&kl,  g_kl);
    cudaGetSymbolAddress((void**)&vh,  g_vh);  cudaGetSymbolAddress((void**)&vl,  g_vl);
    cudaGetSymbolAddress((void**)&oh,  g_oh);  cudaGetSymbolAddress((void**)&ol,  g_ol);
    cudaGetSymbolAddress((void**)&qwh, g_qwh); cudaGetSymbolAddress((void**)&qwl, g_qwl);
    cudaGetSymbolAddress((void**)&kwh, g_kwh); cudaGetSymbolAddress((void**)&kwl, g_kwl);
    cudaGetSymbolAddress((void**)&vwh, g_vwh); cudaGetSymbolAddress((void**)&vwl, g_vwl);
    cudaGetSymbolAddress((void**)&pwh, g_pwh); cudaGetSymbolAddress((void**)&pwl, g_pwl);

    cudaFuncSetAttribute(gemm_bf16<0>, cudaFuncAttributeMaxDynamicSharedMemorySize, GEMM_SMEM);
    cudaFuncSetAttribute(gemm_bf16<1>, cudaFuncAttributeMaxDynamicSharedMemorySize, GEMM_SMEM);
    cudaFuncSetAttribute(gemm_bf16<2>, cudaFuncAttributeMaxDynamicSharedMemorySize, GEMM_SMEM);
    cudaFuncSetAttribute(gemm_bf16<3>, cudaFuncAttributeMaxDynamicSharedMemorySize, GEMM_SMEM);
    cudaFuncSetAttribute(gemm_bf16<4>, cudaFuncAttributeMaxDynamicSharedMemorySize, GEMM_SMEM);

    gn_stats_kernel<<<NG, 256>>>(x);
    gn_apply_t_kernel<<<dim3(HWN / 32, CCH / 32), dim3(32, 8)>>>(x, gamma, beta, hnh, hnl);

    const int nw = CCH * CCH;
    split_kernel<<<nw / 256, 256>>>(qw, qwh, qwl, nw);
    split_kernel<<<nw / 256, 256>>>(kw, kwh, kwl, nw);
    split_kernel<<<nw / 256, 256>>>(vw, vwh, vwl, nw);
    split_kernel<<<nw / 256, 256>>>(pw, pwh, pwl, nw);

    const float scale = 0.04419417382415922f;  // 512^-0.5

    // Q = hn @ qw^T  -> split planes [HW, C]
    gemm_bf16<0><<<dim3(4, 72), 256, GEMM_SMEM>>>(hnh, hnl, qwh, qwl, qb, nullptr,
                                                  nullptr, qh, ql, CCH, CCH, CCH, CCH, 0.f);
    // K = hn @ kw^T
    gemm_bf16<0><<<dim3(4, 72), 256, GEMM_SMEM>>>(hnh, hnl, kwh, kwl, kb, nullptr,
                                                  nullptr, kh, kl, CCH, CCH, CCH, CCH, 0.f);
    // V = vw @ hn^T  -> split planes [C, HW]
    gemm_bf16<1><<<dim3(72, 4), 256, GEMM_SMEM>>>(vwh, vwl, hnh, hnl, vb, nullptr,
                                                  nullptr, vh, vl, CCH, CCH, CCH, HWN, 0.f);
    // S = scale * (Q @ K^T)  -> fp32 [HW, HW]
    gemm_bf16<2><<<dim3(72, 72), 256, GEMM_SMEM>>>(qh, ql, kh, kl, nullptr, nullptr,
                                                   s, nullptr, nullptr, CCH, CCH, CCH, HWN, scale);

    softmax_kernel<<<HWN, 256>>>();

    // O = attn @ V^T  -> split planes [HW, C]
    gemm_bf16<3><<<dim3(4, 72), 256, GEMM_SMEM>>>(sh, sl, vh, vl, nullptr, nullptr,
                                                  nullptr, oh, ol, HWN, HWN, HWN, CCH, 0.f);
    // out = pw @ O^T + pb + x  -> fp32 [C, HW]
    gemm_bf16<4><<<dim3(72, 4), 256, GEMM_SMEM>>>(pwh, pwl, oh, ol, pb, x,
                                                  out, nullptr, nullptr, CCH, CCH, CCH, HWN, 0.f);
}

// round 7
// speedup vs baseline: 6.5682x; 2.4273x over previous
#include <cuda_runtime.h>
#include <cuda_fp16.h>
#include <math.h>
#include <stdint.h>

#define HWN 9216
#define CCH 512
#define NG  32
#define CPG 16

typedef __half fp16;

// ---- scratch (static device globals) ----
__device__ fp16  g_s [(size_t)HWN * HWN];          // scores / attn, fp16 (170 MB)
__device__ fp16  g_hn[(size_t)HWN * CCH];          // groupnorm out, [HW, C]
__device__ fp16  g_q [(size_t)HWN * CCH];          // q, [HW, C]
__device__ fp16  g_k [(size_t)HWN * CCH];          // k, [HW, C]
__device__ fp16  g_v [(size_t)CCH * HWN];          // v, [C, HW]
__device__ fp16  g_o [(size_t)HWN * CCH];          // attn out, [HW, C]
__device__ fp16  g_qw[CCH * CCH], g_kw[CCH * CCH];
__device__ fp16  g_vw[CCH * CCH], g_pw[CCH * CCH];
__device__ float g_stats[NG * 2];

// ---------------------------------------------------------------------------
// helpers
// ---------------------------------------------------------------------------
__device__ __forceinline__ uint32_t smem_u32(const void* p) {
    uint32_t a;
    asm("{ .reg .u64 t; cvta.to.shared.u64 t, %1; cvt.u32.u64 %0, t; }" : "=r"(a) : "l"(p));
    return a;
}
#define SWZ(x) ((x) ^ (((x) >> 3) & 0x70))

__device__ __forceinline__ void cp_async16(uint32_t saddr, const void* gaddr) {
    asm volatile("cp.async.cg.shared.global [%0], [%1], 16;" :: "r"(saddr), "l"(gaddr));
}
__device__ __forceinline__ void cp_commit() { asm volatile("cp.async.commit_group;"); }
#define CP_WAIT1() asm volatile("cp.async.wait_group 1;")

__device__ __forceinline__ void ldm_x4(uint32_t* r, uint32_t addr) {
    asm volatile("ldmatrix.sync.aligned.m8n8.x4.shared.b16 {%0,%1,%2,%3}, [%4];"
                 : "=r"(r[0]), "=r"(r[1]), "=r"(r[2]), "=r"(r[3]) : "r"(addr));
}
__device__ __forceinline__ void mma16816(float* d, const uint32_t* a, uint32_t b0, uint32_t b1) {
    asm volatile(
        "mma.sync.aligned.m16n8k16.row.col.f32.f16.f16.f32 "
        "{%0,%1,%2,%3}, {%4,%5,%6,%7}, {%8,%9}, {%0,%1,%2,%3};"
        : "+f"(d[0]), "+f"(d[1]), "+f"(d[2]), "+f"(d[3])
        : "r"(a[0]), "r"(a[1]), "r"(a[2]), "r"(a[3]), "r"(b0), "r"(b1));
}

__device__ __forceinline__ uint32_t pack_h2(float a, float b) {
    __half2 h = __floats2half2_rn(a, b);
    return *(uint32_t*)&h;
}

// ---------------------------------------------------------------------------
// GroupNorm stats
// ---------------------------------------------------------------------------
__global__ void gn_stats_kernel(const float* __restrict__ x) {
    const int g = blockIdx.x;
    const float4* xp = (const float4*)(x + (size_t)g * CPG * HWN);
    const int n4 = (CPG * HWN) / 4;
    float s = 0.f, s2 = 0.f;
    for (int i = threadIdx.x; i < n4; i += 256) {
        float4 v = xp[i];
        s  += v.x + v.y + v.z + v.w;
        s2 += v.x * v.x + v.y * v.y + v.z * v.z + v.w * v.w;
    }
    __shared__ float rs[256], rq[256];
    rs[threadIdx.x] = s; rq[threadIdx.x] = s2;
    __syncthreads();
    for (int o = 128; o > 0; o >>= 1) {
        if (threadIdx.x < o) {
            rs[threadIdx.x] += rs[threadIdx.x + o];
            rq[threadIdx.x] += rq[threadIdx.x + o];
        }
        __syncthreads();
    }
    if (threadIdx.x == 0) {
        const float inv  = 1.0f / (float)(CPG * HWN);
        const float mean = rs[0] * inv;
        const float var  = rq[0] * inv - mean * mean;
        g_stats[2 * g]     = mean;
        g_stats[2 * g + 1] = rsqrtf(var + 1e-6f);
    }
}

// ---------------------------------------------------------------------------
// GroupNorm apply + transpose: x [C, HW] -> hn fp16 [HW, C]
// ---------------------------------------------------------------------------
__global__ void gn_apply_t_kernel(const float* __restrict__ x,
                                  const float* __restrict__ gamma,
                                  const float* __restrict__ beta,
                                  fp16* __restrict__ out) {
    __shared__ float t[32][33];
    const int i0 = blockIdx.x * 32, c0 = blockIdx.y * 32;
    const int tx = threadIdx.x, ty = threadIdx.y;
#pragma unroll
    for (int k = 0; k < 32; k += 8) {
        const int c = c0 + ty + k;
        const int g = c >> 4;
        const float mean = g_stats[2 * g], rstd = g_stats[2 * g + 1];
        const float ga = gamma[c] * rstd;
        const float be = beta[c] - mean * ga;
        t[ty + k][tx] = x[(size_t)c * HWN + i0 + tx] * ga + be;
    }
    __syncthreads();
#pragma unroll
    for (int k = 0; k < 32; k += 8)
        out[(size_t)(i0 + ty + k) * CCH + c0 + tx] = __float2half(t[tx][ty + k]);
}

// ---------------------------------------------------------------------------
// fp32 -> fp16 convert (weights)
// ---------------------------------------------------------------------------
__global__ void cvt_kernel(const float* __restrict__ w, fp16* __restrict__ h, int n) {
    const int i = blockIdx.x * 256 + threadIdx.x;
    if (i < n) h[i] = __float2half(w[i]);
}

// ---------------------------------------------------------------------------
// fp16 GEMM: D[M,N] = A[M,K] @ B[N,K]^T, fp32 accumulate.
// Tile 128x128, BK=64, 8 warps (64x32 per warp), 3-stage cp.async pipeline.
// EPI: 0 = fp16 out + bias[n]   1 = fp16 out + bias[m]
//      2 = fp16 out * alpha     3 = fp16 out
//      4 = fp32 out + bias[m] + resid[m*ldc+n]
// SMEM: 3 stages x (16KB A + 16KB B) = 96 KB -> 2 CTAs/SM
// ---------------------------------------------------------------------------
#define STG_A(s) ((s) * 16384)
#define STG_B(s) (49152 + (s) * 16384)
#define GEMM_SMEM 98304

__device__ __forceinline__ void load_stage(
    uint32_t sbA, uint32_t sbB,
    const fp16* __restrict__ Ap, const fp16* __restrict__ Bp,
    int bm, int bn, int lda, int ldb, int k0, int tid)
{
#pragma unroll
    for (int r = 0; r < 4; r++) {
        const int idx = tid + (r << 8);        // 0..1023
        const int row = idx >> 3, c8 = idx & 7;
        const uint32_t off = SWZ((row << 7) + (c8 << 4));
        cp_async16(sbA + off, Ap + (size_t)(bm + row) * lda + k0 + (c8 << 3));
        cp_async16(sbB + off, Bp + (size_t)(bn + row) * ldb + k0 + (c8 << 3));
    }
}

template <int EPI>
__global__ void __launch_bounds__(256, 2) gemm_fp16(
    const fp16* __restrict__ A, const fp16* __restrict__ B,
    const float* __restrict__ bias, const float* __restrict__ resid,
    float* __restrict__ Cf, fp16* __restrict__ Ch,
    int K, int lda, int ldb, int ldc, float alpha)
{
    extern __shared__ char smem[];
    const uint32_t sb = smem_u32(smem);
    const int tid  = threadIdx.x;
    const int lane = tid & 31, warp = tid >> 5;
    const int wm = (warp >> 2) * 64;
    const int wn = (warp & 3) * 32;
    const int bm = blockIdx.y * 128;
    const int bn = blockIdx.x * 128;

    float acc[4][4][4];
#pragma unroll
    for (int i = 0; i < 4; i++)
#pragma unroll
        for (int j = 0; j < 4; j++) {
            acc[i][j][0] = 0.f; acc[i][j][1] = 0.f;
            acc[i][j][2] = 0.f; acc[i][j][3] = 0.f;
        }

    const int NCH = K >> 6;

    load_stage(sb + STG_A(0), sb + STG_B(0), A, B, bm, bn, lda, ldb, 0,  tid);
    cp_commit();
    load_stage(sb + STG_A(1), sb + STG_B(1), A, B, bm, bn, lda, ldb, 64, tid);
    cp_commit();

    const int lr  = lane & 7;
    const int sel = lane >> 3;
    const int a_row  = wm + lr + (sel & 1) * 8;
    const int a_kb   = (sel >> 1) * 16;
    const int b_row0 = wn + lr + ((sel >> 1) & 1) * 8;
    const int b_kb   = (sel & 1) * 16;

#pragma unroll 1
    for (int c = 0; c < NCH; ++c) {
        CP_WAIT1();
        __syncthreads();

        const int cn = c + 2;
        if (cn < NCH)
            load_stage(sb + STG_A(cn % 3), sb + STG_B(cn % 3), A, B,
                       bm, bn, lda, ldb, cn << 6, tid);
        cp_commit();

        const uint32_t sA = sb + STG_A(c % 3);
        const uint32_t sB = sb + STG_B(c % 3);
#pragma unroll
        for (int kk = 0; kk < 4; ++kk) {
            uint32_t af[4][4], bfr[2][4];
#pragma unroll
            for (int mi = 0; mi < 4; ++mi)
                ldm_x4(af[mi], sA + SWZ(((a_row + mi * 16) << 7) + kk * 32 + a_kb));
#pragma unroll
            for (int nj = 0; nj < 2; ++nj)
                ldm_x4(bfr[nj], sB + SWZ(((b_row0 + nj * 16) << 7) + kk * 32 + b_kb));
#pragma unroll
            for (int mi = 0; mi < 4; ++mi)
#pragma unroll
                for (int nj = 0; nj < 4; ++nj)
                    mma16816(acc[mi][nj], af[mi],
                             bfr[nj >> 1][(nj & 1) * 2], bfr[nj >> 1][(nj & 1) * 2 + 1]);
        }
        __syncthreads();
    }

    // epilogue
#pragma unroll
    for (int mi = 0; mi < 4; ++mi) {
#pragma unroll
        for (int nj = 0; nj < 4; ++nj) {
            const int r0 = bm + wm + mi * 16 + (lane >> 2);
            const int c0 = bn + wn + nj * 8 + (lane & 3) * 2;
            float v0 = acc[mi][nj][0], v1 = acc[mi][nj][1];
            float v2 = acc[mi][nj][2], v3 = acc[mi][nj][3];
            if (EPI == 0) {
                const float b0 = bias[c0], b1 = bias[c0 + 1];
                v0 += b0; v1 += b1; v2 += b0; v3 += b1;
            } else if (EPI == 1) {
                v0 += bias[r0];     v1 += bias[r0];
                v2 += bias[r0 + 8]; v3 += bias[r0 + 8];
            } else if (EPI == 2) {
                v0 *= alpha; v1 *= alpha; v2 *= alpha; v3 *= alpha;
            } else if (EPI == 4) {
                const float2 ra = *(const float2*)(resid + (size_t)r0 * ldc + c0);
                const float2 rb = *(const float2*)(resid + (size_t)(r0 + 8) * ldc + c0);
                v0 += bias[r0] + ra.x;     v1 += bias[r0] + ra.y;
                v2 += bias[r0 + 8] + rb.x; v3 += bias[r0 + 8] + rb.y;
            }
            if (EPI == 4) {
                *(float2*)(Cf + (size_t)r0 * ldc + c0)       = make_float2(v0, v1);
                *(float2*)(Cf + (size_t)(r0 + 8) * ldc + c0) = make_float2(v2, v3);
            } else {
                *(uint32_t*)(Ch + (size_t)r0 * ldc + c0)       = pack_h2(v0, v1);
                *(uint32_t*)(Ch + (size_t)(r0 + 8) * ldc + c0) = pack_h2(v2, v3);
            }
        }
    }
}

// ---------------------------------------------------------------------------
// Row softmax on fp16 g_s, in place. Row staged as fp32 in SMEM.
// ---------------------------------------------------------------------------
__global__ void softmax_kernel() {
    __shared__ float row[HWN];          // 36.9 KB
    __shared__ float red[256];
    const int r = blockIdx.x, tid = threadIdx.x;
    uint4* sp = (uint4*)(g_s + (size_t)r * HWN);   // 8 halves per uint4

    float mx = -1e30f;
    for (int i = tid; i < HWN / 8; i += 256) {
        uint4 u = sp[i];
        const __half2* h = (const __half2*)&u;
#pragma unroll
        for (int j = 0; j < 4; j++) {
            float2 f = __half22float2(h[j]);
            row[i * 8 + j * 2]     = f.x;
            row[i * 8 + j * 2 + 1] = f.y;
            mx = fmaxf(mx, fmaxf(f.x, f.y));
        }
    }
    red[tid] = mx; __syncthreads();
    for (int o = 128; o > 0; o >>= 1) {
        if (tid < o) red[tid] = fmaxf(red[tid], red[tid + o]);
        __syncthreads();
    }
    mx = red[0];
    __syncthreads();

    float s = 0.f;
    for (int i = tid; i < HWN; i += 256) {
        // strided fp32 pass is fine; recompute layout linearly
    }
    for (int i = tid; i < HWN / 4; i += 256) {
        float4* rp = (float4*)row;
        float4 v = rp[i];
        v.x = __expf(v.x - mx); v.y = __expf(v.y - mx);
        v.z = __expf(v.z - mx); v.w = __expf(v.w - mx);
        rp[i] = v;
        s += v.x + v.y + v.z + v.w;
    }
    red[tid] = s; __syncthreads();
    for (int o = 128; o > 0; o >>= 1) {
        if (tid < o) red[tid] += red[tid + o];
        __syncthreads();
    }
    const float inv = 1.0f / red[0];
    __syncthreads();

    for (int i = tid; i < HWN / 8; i += 256) {
        uint4 u;
        uint32_t* up = (uint32_t*)&u;
#pragma unroll
        for (int j = 0; j < 4; j++)
            up[j] = pack_h2(row[i * 8 + j * 2] * inv, row[i * 8 + j * 2 + 1] * inv);
        sp[i] = u;
    }
}

// ---------------------------------------------------------------------------
// Launch
// ---------------------------------------------------------------------------
extern "C" void kernel_launch(void* const* d_in, const int* in_sizes, int n_in,
                              void* d_out, int out_size)
{
    const float* x     = (const float*)d_in[0];
    const float* gamma = (const float*)d_in[1];
    const float* beta  = (const float*)d_in[2];
    const float* qw    = (const float*)d_in[3];
    const float* qb    = (const float*)d_in[4];
    const float* kw    = (const float*)d_in[5];
    const float* kb    = (const float*)d_in[6];
    const float* vw    = (const float*)d_in[7];
    const float* vb    = (const float*)d_in[8];
    const float* pw    = (const float*)d_in[9];
    const float* pb    = (const float*)d_in[10];
    float* out = (float*)d_out;

    fp16 *s, *hn, *q, *k, *v, *o, *qwh, *kwh, *vwh, *pwh;
    cudaGetSymbolAddress((void**)&s,   g_s);
    cudaGetSymbolAddress((void**)&hn,  g_hn);
    cudaGetSymbolAddress((void**)&q,   g_q);
    cudaGetSymbolAddress((void**)&k,   g_k);
    cudaGetSymbolAddress((void**)&v,   g_v);
    cudaGetSymbolAddress((void**)&o,   g_o);
    cudaGetSymbolAddress((void**)&qwh, g_qw);
    cudaGetSymbolAddress((void**)&kwh, g_kw);
    cudaGetSymbolAddress((void**)&vwh, g_vw);
    cudaGetSymbolAddress((void**)&pwh, g_pw);

    cudaFuncSetAttribute(gemm_fp16<0>, cudaFuncAttributeMaxDynamicSharedMemorySize, GEMM_SMEM);
    cudaFuncSetAttribute(gemm_fp16<1>, cudaFuncAttributeMaxDynamicSharedMemorySize, GEMM_SMEM);
    cudaFuncSetAttribute(gemm_fp16<2>, cudaFuncAttributeMaxDynamicSharedMemorySize, GEMM_SMEM);
    cudaFuncSetAttribute(gemm_fp16<3>, cudaFuncAttributeMaxDynamicSharedMemorySize, GEMM_SMEM);
    cudaFuncSetAttribute(gemm_fp16<4>, cudaFuncAttributeMaxDynamicSharedMemorySize, GEMM_SMEM);

    gn_stats_kernel<<<NG, 256>>>(x);
    gn_apply_t_kernel<<<dim3(HWN / 32, CCH / 32), dim3(32, 8)>>>(x, gamma, beta, hn);

    const int nw = CCH * CCH;
    cvt_kernel<<<nw / 256, 256>>>(qw, qwh, nw);
    cvt_kernel<<<nw / 256, 256>>>(kw, kwh, nw);
    cvt_kernel<<<nw / 256, 256>>>(vw, vwh, nw);
    cvt_kernel<<<nw / 256, 256>>>(pw, pwh, nw);

    const float scale = 0.04419417382415922f;  // 512^-0.5

    // Q = hn @ qw^T  -> fp16 [HW, C]
    gemm_fp16<0><<<dim3(4, 72), 256, GEMM_SMEM>>>(hn, qwh, qb, nullptr, nullptr, q,
                                                  CCH, CCH, CCH, CCH, 0.f);
    // K = hn @ kw^T  -> fp16 [HW, C]
    gemm_fp16<0><<<dim3(4, 72), 256, GEMM_SMEM>>>(hn, kwh, kb, nullptr, nullptr, k,
                                                  CCH, CCH, CCH, CCH, 0.f);
    // V = vw @ hn^T  -> fp16 [C, HW]
    gemm_fp16<1><<<dim3(72, 4), 256, GEMM_SMEM>>>(vwh, hn, vb, nullptr, nullptr, v,
                                                  CCH, CCH, CCH, HWN, 0.f);
    // S = scale * (Q @ K^T)  -> fp16 [HW, HW]
    gemm_fp16<2><<<dim3(72, 72), 256, GEMM_SMEM>>>(q, k, nullptr, nullptr, nullptr, s,
                                                   CCH, CCH, CCH, HWN, scale);

    softmax_kernel<<<HWN, 256>>>();

    // O = attn @ V^T  -> fp16 [HW, C]
    gemm_fp16<3><<<dim3(4, 72), 256, GEMM_SMEM>>>(s, v, nullptr, nullptr, nullptr, o,
                                                  HWN, HWN, HWN, CCH, 0.f);
    // out = pw @ O^T + pb + x  -> fp32 [C, HW]
    gemm_fp16<4><<<dim3(72, 4), 256, GEMM_SMEM>>>(pwh, o, pb, x, out, nullptr,
                                                  CCH, CCH, CCH, HWN, 0.f);
}

// round 8
// speedup vs baseline: 7.3578x; 1.1202x over previous
#include <cuda_runtime.h>
#include <cuda_fp16.h>
#include <math.h>
#include <stdint.h>

#define HWN 9216
#define CCH 512
#define NG  32
#define CPG 16

typedef __half fp16;

// ---- scratch (static device globals) ----
__device__ fp16  g_s [(size_t)HWN * HWN];          // P = exp(scores), fp16 (170 MB)
__device__ fp16  g_hn[(size_t)HWN * CCH];
__device__ fp16  g_q [(size_t)HWN * CCH];
__device__ fp16  g_k [(size_t)HWN * CCH];
__device__ fp16  g_v [(size_t)CCH * HWN];          // v, [C, HW]
__device__ fp16  g_o [(size_t)HWN * CCH];
__device__ fp16  g_qw[CCH * CCH], g_kw[CCH * CCH];
__device__ fp16  g_vw[CCH * CCH], g_pw[CCH * CCH];
__device__ float g_rowpart[36 * HWN];              // per-CTA-column partial row sums
__device__ float g_dinv[HWN];                      // 1 / denom
__device__ float g_stats[NG * 2];

// ---------------------------------------------------------------------------
// helpers
// ---------------------------------------------------------------------------
__device__ __forceinline__ uint32_t smem_u32(const void* p) {
    uint32_t a;
    asm("{ .reg .u64 t; cvta.to.shared.u64 t, %1; cvt.u32.u64 %0, t; }" : "=r"(a) : "l"(p));
    return a;
}
#define SWZ(x) ((x) ^ (((x) >> 3) & 0x70))

__device__ __forceinline__ void cp_async16(uint32_t saddr, const void* gaddr) {
    asm volatile("cp.async.cg.shared.global [%0], [%1], 16;" :: "r"(saddr), "l"(gaddr));
}
__device__ __forceinline__ void cp_commit() { asm volatile("cp.async.commit_group;"); }
#define CP_WAIT1() asm volatile("cp.async.wait_group 1;")

__device__ __forceinline__ void ldm_x4(uint32_t* r, uint32_t addr) {
    asm volatile("ldmatrix.sync.aligned.m8n8.x4.shared.b16 {%0,%1,%2,%3}, [%4];"
                 : "=r"(r[0]), "=r"(r[1]), "=r"(r[2]), "=r"(r[3]) : "r"(addr));
}
__device__ __forceinline__ void mma16816(float* d, const uint32_t* a, uint32_t b0, uint32_t b1) {
    asm volatile(
        "mma.sync.aligned.m16n8k16.row.col.f32.f16.f16.f32 "
        "{%0,%1,%2,%3}, {%4,%5,%6,%7}, {%8,%9}, {%0,%1,%2,%3};"
        : "+f"(d[0]), "+f"(d[1]), "+f"(d[2]), "+f"(d[3])
        : "r"(a[0]), "r"(a[1]), "r"(a[2]), "r"(a[3]), "r"(b0), "r"(b1));
}

__device__ __forceinline__ uint32_t pack_h2(float a, float b) {
    __half2 h = __floats2half2_rn(a, b);
    return *(uint32_t*)&h;
}

// ---------------------------------------------------------------------------
// GroupNorm stats
// ---------------------------------------------------------------------------
__global__ void gn_stats_kernel(const float* __restrict__ x) {
    const int g = blockIdx.x;
    const float4* xp = (const float4*)(x + (size_t)g * CPG * HWN);
    const int n4 = (CPG * HWN) / 4;
    float s = 0.f, s2 = 0.f;
    for (int i = threadIdx.x; i < n4; i += 256) {
        float4 v = xp[i];
        s  += v.x + v.y + v.z + v.w;
        s2 += v.x * v.x + v.y * v.y + v.z * v.z + v.w * v.w;
    }
    __shared__ float rs[256], rq[256];
    rs[threadIdx.x] = s; rq[threadIdx.x] = s2;
    __syncthreads();
    for (int o = 128; o > 0; o >>= 1) {
        if (threadIdx.x < o) {
            rs[threadIdx.x] += rs[threadIdx.x + o];
            rq[threadIdx.x] += rq[threadIdx.x + o];
        }
        __syncthreads();
    }
    if (threadIdx.x == 0) {
        const float inv  = 1.0f / (float)(CPG * HWN);
        const float mean = rs[0] * inv;
        const float var  = rq[0] * inv - mean * mean;
        g_stats[2 * g]     = mean;
        g_stats[2 * g + 1] = rsqrtf(var + 1e-6f);
    }
}

// ---------------------------------------------------------------------------
// GroupNorm apply + transpose: x [C, HW] -> hn fp16 [HW, C]
// ---------------------------------------------------------------------------
__global__ void gn_apply_t_kernel(const float* __restrict__ x,
                                  const float* __restrict__ gamma,
                                  const float* __restrict__ beta,
                                  fp16* __restrict__ out) {
    __shared__ float t[32][33];
    const int i0 = blockIdx.x * 32, c0 = blockIdx.y * 32;
    const int tx = threadIdx.x, ty = threadIdx.y;
#pragma unroll
    for (int k = 0; k < 32; k += 8) {
        const int c = c0 + ty + k;
        const int g = c >> 4;
        const float mean = g_stats[2 * g], rstd = g_stats[2 * g + 1];
        const float ga = gamma[c] * rstd;
        const float be = beta[c] - mean * ga;
        t[ty + k][tx] = x[(size_t)c * HWN + i0 + tx] * ga + be;
    }
    __syncthreads();
#pragma unroll
    for (int k = 0; k < 32; k += 8)
        out[(size_t)(i0 + ty + k) * CCH + c0 + tx] = __float2half(t[tx][ty + k]);
}

__global__ void cvt_kernel(const float* __restrict__ w, fp16* __restrict__ h, int n) {
    const int i = blockIdx.x * 256 + threadIdx.x;
    if (i < n) h[i] = __float2half(w[i]);
}

// ---------------------------------------------------------------------------
// denom reduce: dinv[i] = 1 / sum_b rowpart[b][i]
// ---------------------------------------------------------------------------
__global__ void denom_kernel() {
    const int i = blockIdx.x * 256 + threadIdx.x;
    float s = 0.f;
#pragma unroll
    for (int b = 0; b < 36; b++) s += g_rowpart[b * HWN + i];
    g_dinv[i] = 1.0f / s;
}

// ---------------------------------------------------------------------------
// NARROW fp16 GEMM (128x128), used for QKV + proj.  D = A[M,K] @ B[N,K]^T
// EPI: 0 = fp16 out + bias[n]   1 = fp16 out + bias[m]
//      4 = fp32 out + bias[m] + resid[m*ldc+n]
// ---------------------------------------------------------------------------
#define STG_A(s) ((s) * 16384)
#define STG_B(s) (49152 + (s) * 16384)
#define GEMM_SMEM 98304

__device__ __forceinline__ void load_stage(
    uint32_t sbA, uint32_t sbB,
    const fp16* __restrict__ Ap, const fp16* __restrict__ Bp,
    int bm, int bn, int lda, int ldb, int k0, int tid)
{
#pragma unroll
    for (int r = 0; r < 4; r++) {
        const int idx = tid + (r << 8);
        const int row = idx >> 3, c8 = idx & 7;
        const uint32_t off = SWZ((row << 7) + (c8 << 4));
        cp_async16(sbA + off, Ap + (size_t)(bm + row) * lda + k0 + (c8 << 3));
        cp_async16(sbB + off, Bp + (size_t)(bn + row) * ldb + k0 + (c8 << 3));
    }
}

template <int EPI>
__global__ void __launch_bounds__(256, 2) gemm_fp16(
    const fp16* __restrict__ A, const fp16* __restrict__ B,
    const float* __restrict__ bias, const float* __restrict__ resid,
    float* __restrict__ Cf, fp16* __restrict__ Ch,
    int K, int lda, int ldb, int ldc)
{
    extern __shared__ char smem[];
    const uint32_t sb = smem_u32(smem);
    const int tid  = threadIdx.x;
    const int lane = tid & 31, warp = tid >> 5;
    const int wm = (warp >> 2) * 64;
    const int wn = (warp & 3) * 32;
    const int bm = blockIdx.y * 128;
    const int bn = blockIdx.x * 128;

    float acc[4][4][4];
#pragma unroll
    for (int i = 0; i < 4; i++)
#pragma unroll
        for (int j = 0; j < 4; j++) {
            acc[i][j][0] = 0.f; acc[i][j][1] = 0.f;
            acc[i][j][2] = 0.f; acc[i][j][3] = 0.f;
        }

    const int NCH = K >> 6;
    load_stage(sb + STG_A(0), sb + STG_B(0), A, B, bm, bn, lda, ldb, 0,  tid);
    cp_commit();
    load_stage(sb + STG_A(1), sb + STG_B(1), A, B, bm, bn, lda, ldb, 64, tid);
    cp_commit();

    const int lr  = lane & 7;
    const int sel = lane >> 3;
    const int a_row  = wm + lr + (sel & 1) * 8;
    const int a_kb   = (sel >> 1) * 16;
    const int b_row0 = wn + lr + ((sel >> 1) & 1) * 8;
    const int b_kb   = (sel & 1) * 16;

#pragma unroll 1
    for (int c = 0; c < NCH; ++c) {
        CP_WAIT1();
        __syncthreads();
        const int cn = c + 2;
        if (cn < NCH)
            load_stage(sb + STG_A(cn % 3), sb + STG_B(cn % 3), A, B,
                       bm, bn, lda, ldb, cn << 6, tid);
        cp_commit();

        const uint32_t sA = sb + STG_A(c % 3);
        const uint32_t sB = sb + STG_B(c % 3);
#pragma unroll
        for (int kk = 0; kk < 4; ++kk) {
            uint32_t af[4][4], bfr[2][4];
#pragma unroll
            for (int mi = 0; mi < 4; ++mi)
                ldm_x4(af[mi], sA + SWZ(((a_row + mi * 16) << 7) + kk * 32 + a_kb));
#pragma unroll
            for (int nj = 0; nj < 2; ++nj)
                ldm_x4(bfr[nj], sB + SWZ(((b_row0 + nj * 16) << 7) + kk * 32 + b_kb));
#pragma unroll
            for (int mi = 0; mi < 4; ++mi)
#pragma unroll
                for (int nj = 0; nj < 4; ++nj)
                    mma16816(acc[mi][nj], af[mi],
                             bfr[nj >> 1][(nj & 1) * 2], bfr[nj >> 1][(nj & 1) * 2 + 1]);
        }
        __syncthreads();
    }

#pragma unroll
    for (int mi = 0; mi < 4; ++mi) {
#pragma unroll
        for (int nj = 0; nj < 4; ++nj) {
            const int r0 = bm + wm + mi * 16 + (lane >> 2);
            const int c0 = bn + wn + nj * 8 + (lane & 3) * 2;
            float v0 = acc[mi][nj][0], v1 = acc[mi][nj][1];
            float v2 = acc[mi][nj][2], v3 = acc[mi][nj][3];
            if (EPI == 0) {
                const float b0 = bias[c0], b1 = bias[c0 + 1];
                v0 += b0; v1 += b1; v2 += b0; v3 += b1;
            } else if (EPI == 1) {
                v0 += bias[r0];     v1 += bias[r0];
                v2 += bias[r0 + 8]; v3 += bias[r0 + 8];
            } else if (EPI == 4) {
                const float2 ra = *(const float2*)(resid + (size_t)r0 * ldc + c0);
                const float2 rb = *(const float2*)(resid + (size_t)(r0 + 8) * ldc + c0);
                v0 += bias[r0] + ra.x;     v1 += bias[r0] + ra.y;
                v2 += bias[r0 + 8] + rb.x; v3 += bias[r0 + 8] + rb.y;
            }
            if (EPI == 4) {
                *(float2*)(Cf + (size_t)r0 * ldc + c0)       = make_float2(v0, v1);
                *(float2*)(Cf + (size_t)(r0 + 8) * ldc + c0) = make_float2(v2, v3);
            } else {
                *(uint32_t*)(Ch + (size_t)r0 * ldc + c0)       = pack_h2(v0, v1);
                *(uint32_t*)(Ch + (size_t)(r0 + 8) * ldc + c0) = pack_h2(v2, v3);
            }
        }
    }
}

// ---------------------------------------------------------------------------
// WIDE fp16 GEMM (128x256), warp tile 64x64.  D = A[M,K] @ B[N,K]^T
// EPI: 6 = P = exp(alpha * s), write fp16 + partial row sums -> g_rowpart
//      5 = fp16 out * dinv[row]  (AV normalize)
// SMEM: 3 x (A 16KB) + 3 x (B 32KB) = 144 KB -> 1 CTA/SM
// ---------------------------------------------------------------------------
#define WSTG_A(s) ((s) * 16384)
#define WSTG_B(s) (49152 + (s) * 32768)
#define WGEMM_SMEM 147456

__device__ __forceinline__ void load_stage_w(
    uint32_t sbA, uint32_t sbB,
    const fp16* __restrict__ Ap, const fp16* __restrict__ Bp,
    int bm, int bn, int lda, int ldb, int k0, int tid)
{
#pragma unroll
    for (int r = 0; r < 4; r++) {
        const int idx = tid + (r << 8);
        const int row = idx >> 3, c8 = idx & 7;
        const uint32_t off = SWZ((row << 7) + (c8 << 4));
        cp_async16(sbA + off, Ap + (size_t)(bm + row) * lda + k0 + (c8 << 3));
    }
#pragma unroll
    for (int r = 0; r < 8; r++) {
        const int idx = tid + (r << 8);
        const int row = idx >> 3, c8 = idx & 7;
        const uint32_t off = SWZ((row << 7) + (c8 << 4));
        cp_async16(sbB + off, Bp + (size_t)(bn + row) * ldb + k0 + (c8 << 3));
    }
}

template <int EPI>
__global__ void __launch_bounds__(256, 1) gemm_fp16_w(
    const fp16* __restrict__ A, const fp16* __restrict__ B,
    fp16* __restrict__ Ch, int K, int lda, int ldb, int ldc, float alpha)
{
    extern __shared__ char smem[];
    const uint32_t sb = smem_u32(smem);
    const int tid  = threadIdx.x;
    const int lane = tid & 31, warp = tid >> 5;
    const int wm = (warp >> 2) * 64;
    const int wn = (warp & 3) * 64;
    const int bm = blockIdx.y * 128;
    const int bn = blockIdx.x * 256;

    float acc[4][8][4];
#pragma unroll
    for (int i = 0; i < 4; i++)
#pragma unroll
        for (int j = 0; j < 8; j++) {
            acc[i][j][0] = 0.f; acc[i][j][1] = 0.f;
            acc[i][j][2] = 0.f; acc[i][j][3] = 0.f;
        }

    const int NCH = K >> 6;
    load_stage_w(sb + WSTG_A(0), sb + WSTG_B(0), A, B, bm, bn, lda, ldb, 0,  tid);
    cp_commit();
    load_stage_w(sb + WSTG_A(1), sb + WSTG_B(1), A, B, bm, bn, lda, ldb, 64, tid);
    cp_commit();

    const int lr  = lane & 7;
    const int sel = lane >> 3;
    const int a_row  = wm + lr + (sel & 1) * 8;
    const int a_kb   = (sel >> 1) * 16;
    const int b_row0 = wn + lr + ((sel >> 1) & 1) * 8;
    const int b_kb   = (sel & 1) * 16;

#pragma unroll 1
    for (int c = 0; c < NCH; ++c) {
        CP_WAIT1();
        __syncthreads();
        const int cn = c + 2;
        if (cn < NCH)
            load_stage_w(sb + WSTG_A(cn % 3), sb + WSTG_B(cn % 3), A, B,
                         bm, bn, lda, ldb, cn << 6, tid);
        cp_commit();

        const uint32_t sA = sb + WSTG_A(c % 3);
        const uint32_t sB = sb + WSTG_B(c % 3);
#pragma unroll
        for (int kk = 0; kk < 4; ++kk) {
            uint32_t af[4][4], bfr[4][4];
#pragma unroll
            for (int mi = 0; mi < 4; ++mi)
                ldm_x4(af[mi], sA + SWZ(((a_row + mi * 16) << 7) + kk * 32 + a_kb));
#pragma unroll
            for (int nb = 0; nb < 4; ++nb)
                ldm_x4(bfr[nb], sB + SWZ(((b_row0 + nb * 16) << 7) + kk * 32 + b_kb));
#pragma unroll
            for (int mi = 0; mi < 4; ++mi)
#pragma unroll
                for (int nj = 0; nj < 8; ++nj)
                    mma16816(acc[mi][nj], af[mi],
                             bfr[nj >> 1][(nj & 1) * 2], bfr[nj >> 1][(nj & 1) * 2 + 1]);
        }
        __syncthreads();
    }

    if (EPI == 6) {
        // exp epilogue + deterministic partial row sums
        float rs0[4], rs1[4];
#pragma unroll
        for (int mi = 0; mi < 4; ++mi) { rs0[mi] = 0.f; rs1[mi] = 0.f; }
#pragma unroll
        for (int mi = 0; mi < 4; ++mi) {
#pragma unroll
            for (int nj = 0; nj < 8; ++nj) {
                const int r0 = bm + wm + mi * 16 + (lane >> 2);
                const int c0 = bn + wn + nj * 8 + (lane & 3) * 2;
                float p0 = __expf(acc[mi][nj][0] * alpha);
                float p1 = __expf(acc[mi][nj][1] * alpha);
                float p2 = __expf(acc[mi][nj][2] * alpha);
                float p3 = __expf(acc[mi][nj][3] * alpha);
                rs0[mi] += p0 + p1;
                rs1[mi] += p2 + p3;
                *(uint32_t*)(Ch + (size_t)r0 * ldc + c0)       = pack_h2(p0, p1);
                *(uint32_t*)(Ch + (size_t)(r0 + 8) * ldc + c0) = pack_h2(p2, p3);
            }
        }
        // reduce across the 4 lanes sharing a row
#pragma unroll
        for (int mi = 0; mi < 4; ++mi) {
            rs0[mi] += __shfl_xor_sync(0xffffffffu, rs0[mi], 1);
            rs0[mi] += __shfl_xor_sync(0xffffffffu, rs0[mi], 2);
            rs1[mi] += __shfl_xor_sync(0xffffffffu, rs1[mi], 1);
            rs1[mi] += __shfl_xor_sync(0xffffffffu, rs1[mi], 2);
        }
        __syncthreads();                       // stages no longer needed
        float* ssum = (float*)smem;            // [128][4]
        if ((lane & 3) == 0) {
#pragma unroll
            for (int mi = 0; mi < 4; ++mi) {
                const int rl = wm + mi * 16 + (lane >> 2);
                ssum[rl * 4 + (warp & 3)]       = rs0[mi];
                ssum[(rl + 8) * 4 + (warp & 3)] = rs1[mi];
            }
        }
        __syncthreads();
        if (tid < 128) {
            const float t = ssum[tid * 4] + ssum[tid * 4 + 1] +
                            ssum[tid * 4 + 2] + ssum[tid * 4 + 3];
            g_rowpart[(size_t)blockIdx.x * HWN + bm + tid] = t;
        }
    } else {
        // EPI 5: normalize by 1/denom
#pragma unroll
        for (int mi = 0; mi < 4; ++mi) {
            const int r0 = bm + wm + mi * 16 + (lane >> 2);
            const float d0 = g_dinv[r0], d1 = g_dinv[r0 + 8];
#pragma unroll
            for (int nj = 0; nj < 8; ++nj) {
                const int c0 = bn + wn + nj * 8 + (lane & 3) * 2;
                *(uint32_t*)(Ch + (size_t)r0 * ldc + c0) =
                    pack_h2(acc[mi][nj][0] * d0, acc[mi][nj][1] * d0);
                *(uint32_t*)(Ch + (size_t)(r0 + 8) * ldc + c0) =
                    pack_h2(acc[mi][nj][2] * d1, acc[mi][nj][3] * d1);
            }
        }
    }
}

// ---------------------------------------------------------------------------
// Launch
// ---------------------------------------------------------------------------
extern "C" void kernel_launch(void* const* d_in, const int* in_sizes, int n_in,
                              void* d_out, int out_size)
{
    const float* x     = (const float*)d_in[0];
    const float* gamma = (const float*)d_in[1];
    const float* beta  = (const float*)d_in[2];
    const float* qw    = (const float*)d_in[3];
    const float* qb    = (const float*)d_in[4];
    const float* kw    = (const float*)d_in[5];
    const float* kb    = (const float*)d_in[6];
    const float* vw    = (const float*)d_in[7];
    const float* vb    = (const float*)d_in[8];
    const float* pw    = (const float*)d_in[9];
    const float* pb    = (const float*)d_in[10];
    float* out = (float*)d_out;

    fp16 *s, *hn, *q, *k, *v, *o, *qwh, *kwh, *vwh, *pwh;
    cudaGetSymbolAddress((void**)&s,   g_s);
    cudaGetSymbolAddress((void**)&hn,  g_hn);
    cudaGetSymbolAddress((void**)&q,   g_q);
    cudaGetSymbolAddress((void**)&k,   g_k);
    cudaGetSymbolAddress((void**)&v,   g_v);
    cudaGetSymbolAddress((void**)&o,   g_o);
    cudaGetSymbolAddress((void**)&qwh, g_qw);
    cudaGetSymbolAddress((void**)&kwh, g_kw);
    cudaGetSymbolAddress((void**)&vwh, g_vw);
    cudaGetSymbolAddress((void**)&pwh, g_pw);

    cudaFuncSetAttribute(gemm_fp16<0>, cudaFuncAttributeMaxDynamicSharedMemorySize, GEMM_SMEM);
    cudaFuncSetAttribute(gemm_fp16<1>, cudaFuncAttributeMaxDynamicSharedMemorySize, GEMM_SMEM);
    cudaFuncSetAttribute(gemm_fp16<4>, cudaFuncAttributeMaxDynamicSharedMemorySize, GEMM_SMEM);
    cudaFuncSetAttribute(gemm_fp16_w<5>, cudaFuncAttributeMaxDynamicSharedMemorySize, WGEMM_SMEM);
    cudaFuncSetAttribute(gemm_fp16_w<6>, cudaFuncAttributeMaxDynamicSharedMemorySize, WGEMM_SMEM);

    gn_stats_kernel<<<NG, 256>>>(x);
    gn_apply_t_kernel<<<dim3(HWN / 32, CCH / 32), dim3(32, 8)>>>(x, gamma, beta, hn);

    const int nw = CCH * CCH;
    cvt_kernel<<<nw / 256, 256>>>(qw, qwh, nw);
    cvt_kernel<<<nw / 256, 256>>>(kw, kwh, nw);
    cvt_kernel<<<nw / 256, 256>>>(vw, vwh, nw);
    cvt_kernel<<<nw / 256, 256>>>(pw, pwh, nw);

    const float scale = 0.04419417382415922f;  // 512^-0.5

    // Q = hn @ qw^T -> fp16 [HW, C]
    gemm_fp16<0><<<dim3(4, 72), 256, GEMM_SMEM>>>(hn, qwh, qb, nullptr, nullptr, q,
                                                  CCH, CCH, CCH, CCH);
    // K = hn @ kw^T -> fp16 [HW, C]
    gemm_fp16<0><<<dim3(4, 72), 256, GEMM_SMEM>>>(hn, kwh, kb, nullptr, nullptr, k,
                                                  CCH, CCH, CCH, CCH);
    // V = vw @ hn^T -> fp16 [C, HW]
    gemm_fp16<1><<<dim3(72, 4), 256, GEMM_SMEM>>>(vwh, hn, vb, nullptr, nullptr, v,
                                                  CCH, CCH, CCH, HWN);
    // P = exp(scale * Q @ K^T) -> fp16 [HW, HW], + partial row sums
    gemm_fp16_w<6><<<dim3(36, 72), 256, WGEMM_SMEM>>>(q, k, s, CCH, CCH, CCH, HWN, scale);

    denom_kernel<<<HWN / 256, 256>>>();

    // O = (P @ V^T) * dinv -> fp16 [HW, C]
    gemm_fp16_w<5><<<dim3(2, 72), 256, WGEMM_SMEM>>>(s, v, o, HWN, HWN, HWN, CCH, 0.f);
    // out = pw @ O^T + pb + x -> fp32 [C, HW]
    gemm_fp16<4><<<dim3(72, 4), 256, GEMM_SMEM>>>(pwh, o, pb, x, out, nullptr,
                                                  CCH, CCH, CCH, HWN);
}